// round 13
// baseline (speedup 1.0000x reference)
#include <cuda_runtime.h>

// out[b, r, c] = x[b, r, c] * weight[c], N = 4096 (power of two)
// FINAL (R9 config): memory-roofline kernel — 536.9 MB moved at ~7.17 TB/s
// effective (~90% of 8 TB/s HBM3e spec; remainder is read/write bus
// turnaround, path-independent). Verified across 7 A/Bs: MLP=4 saturates,
// cache policy / occupancy / indexing width / persistence all neutral.
// 4x float4/thread front-batched, exact grid cover, 32-bit indexing,
// thread-invariant weight columns (block chunk == one 4096-col row),
// streaming hints on x/out, regs capped for 8 blocks/SM.

#define THREADS 256
#define UNROLL  4
// block chunk = 1024 float4 = 4096 scalars = exactly one weight row

__global__ void __launch_bounds__(THREADS, 8) scale_lastdim_final_kernel(
    const float4* __restrict__ x4,
    const float*  __restrict__ w,
    float4* __restrict__ out4)
{
    const unsigned t = threadIdx.x;
    const unsigned base = blockIdx.x * (THREADS * UNROLL) + t;

    // (global_col & 4095) == t*4 + k*1024 : block base is a multiple of 4096
    float4 wv[UNROLL];
#pragma unroll
    for (int k = 0; k < UNROLL; k++)
        wv[k] = __ldg((const float4*)(w + k * 1024 + t * 4));  // 16 KB, L1-hit

    // Front-batch 4 independent LDG.128 (streaming: x never reused)
    float4 xv[UNROLL];
#pragma unroll
    for (int k = 0; k < UNROLL; k++)
        xv[k] = __ldcs(&x4[base + k * THREADS]);

#pragma unroll
    for (int k = 0; k < UNROLL; k++) {
        float4 ov;
        ov.x = xv[k].x * wv[k].x;
        ov.y = xv[k].y * wv[k].y;
        ov.z = xv[k].z * wv[k].z;
        ov.w = xv[k].w * wv[k].w;
        __stcs(&out4[base + k * THREADS], ov);
    }
}

extern "C" void kernel_launch(void* const* d_in, const int* in_sizes, int n_in,
                              void* d_out, int out_size)
{
    const float* x = (const float*)d_in[0];
    const float* w = (const float*)d_in[1];
    float* out = (float*)d_out;

    long long n  = (long long)out_size;         // 4*4096*4096 = 67108864
    unsigned n4 = (unsigned)(n >> 2);           // 16777216 float4s
    unsigned blocks = n4 / (THREADS * UNROLL);  // 16384, exact cover

    scale_lastdim_final_kernel<<<blocks, THREADS>>>(
        (const float4*)x, w, (float4*)out);
}

// round 15
// speedup vs baseline: 1.0039x; 1.0039x over previous
#include <cuda_runtime.h>

// out[b, r, c] = x[b, r, c] * weight[c], N = 4096 (power of two)
// Memory-roofline stream (~7.1 TB/s effective, ~89% of 8 TB/s HBM3e spec).
// Block-geometry A/B: 512 threads x UNROLL=4 (MLP=4, the verified saturation
// point), half the CTA count of the 256-thread variant. Block chunk =
// 2048 float4 = two 4096-col rows -> weight cols = t*4 + (k&1)*2048,
// thread-invariant. Streaming hints, exact cover, 32-bit indexing.

#define THREADS 512
#define UNROLL  4
// block chunk = 2048 float4 = 8192 scalars = exactly two weight rows

__global__ void __launch_bounds__(THREADS, 4) scale_lastdim_b512_kernel(
    const float4* __restrict__ x4,
    const float*  __restrict__ w,
    float4* __restrict__ out4)
{
    const unsigned t = threadIdx.x;
    const unsigned base = blockIdx.x * (THREADS * UNROLL) + t;

    // (global_col & 4095) == (t*4 + k*2048) & 4095 == t*4 + (k&1)*2048
    float4 wv[2];
#pragma unroll
    for (int k = 0; k < 2; k++)
        wv[k] = __ldg((const float4*)(w + ((k * 2048 + t * 4) & 4095)));  // L1-hit

    // Front-batch 4 independent LDG.128 (streaming: x never reused)
    float4 xv[UNROLL];
#pragma unroll
    for (int k = 0; k < UNROLL; k++)
        xv[k] = __ldcs(&x4[base + k * THREADS]);

#pragma unroll
    for (int k = 0; k < UNROLL; k++) {
        const float4 wk = wv[k & 1];
        float4 ov;
        ov.x = xv[k].x * wk.x;
        ov.y = xv[k].y * wk.y;
        ov.z = xv[k].z * wk.z;
        ov.w = xv[k].w * wk.w;
        __stcs(&out4[base + k * THREADS], ov);
    }
}

extern "C" void kernel_launch(void* const* d_in, const int* in_sizes, int n_in,
                              void* d_out, int out_size)
{
    const float* x = (const float*)d_in[0];
    const float* w = (const float*)d_in[1];
    float* out = (float*)d_out;

    long long n  = (long long)out_size;         // 4*4096*4096 = 67108864
    unsigned n4 = (unsigned)(n >> 2);           // 16777216 float4s
    unsigned blocks = n4 / (THREADS * UNROLL);  // 8192, exact cover

    scale_lastdim_b512_kernel<<<blocks, THREADS>>>(
        (const float4*)x, w, (float4*)out);
}

// round 17
// speedup vs baseline: 1.0047x; 1.0008x over previous
#include <cuda_runtime.h>

// out[b, r, c] = x[b, r, c] * weight[c], N = 4096 (power of two)
// sm_103a 256-bit memory-op variant: ld/st.global.v8.f32 (LDG.E.256 /
// STG.E.256, Blackwell-only, PTX-reachable). Halves LSU ops and L1tex
// wavefronts per byte vs float4. MLP=4 per thread (verified saturation),
// exact cover, 32-bit indexing, thread-invariant weight (block chunk =
// two 4096-col rows -> wv[k&1]). All accesses 32B-aligned by construction.

#define THREADS 256
#define UNROLL  4
// per thread: 8 floats (32B) per unroll step; block chunk = 8192 scalars = 2 rows

__device__ __forceinline__ void ldg256(float r[8], const float* p) {
    asm volatile("ld.global.v8.f32 {%0,%1,%2,%3,%4,%5,%6,%7}, [%8];"
        : "=f"(r[0]), "=f"(r[1]), "=f"(r[2]), "=f"(r[3]),
          "=f"(r[4]), "=f"(r[5]), "=f"(r[6]), "=f"(r[7])
        : "l"(p));
}

__device__ __forceinline__ void stg256(float* p, const float r[8]) {
    asm volatile("st.global.v8.f32 [%0], {%1,%2,%3,%4,%5,%6,%7,%8};"
        :: "l"(p),
           "f"(r[0]), "f"(r[1]), "f"(r[2]), "f"(r[3]),
           "f"(r[4]), "f"(r[5]), "f"(r[6]), "f"(r[7])
        : "memory");
}

__global__ void __launch_bounds__(THREADS) scale_lastdim_v8_kernel(
    const float* __restrict__ x,
    const float* __restrict__ w,
    float* __restrict__ out)
{
    const unsigned t = threadIdx.x;
    // scalar index of this thread's first element (multiple of 8 -> 32B aligned)
    const unsigned base = blockIdx.x * (THREADS * UNROLL * 8) + t * 8;

    // (global_col & 4095) == (t*8 + k*2048) & 4095 -> period 2 in k
    float wv[2][8];
#pragma unroll
    for (int k = 0; k < 2; k++)
        ldg256(wv[k], w + ((k * 2048 + t * 8) & 4095));   // 16 KB, L1-resident

    // Front-batch 4 independent LDG.E.256
    float xv[UNROLL][8];
#pragma unroll
    for (int k = 0; k < UNROLL; k++)
        ldg256(xv[k], x + base + k * (THREADS * 8));

#pragma unroll
    for (int k = 0; k < UNROLL; k++) {
        float ov[8];
#pragma unroll
        for (int j = 0; j < 8; j++)
            ov[j] = xv[k][j] * wv[k & 1][j];
        stg256(out + base + k * (THREADS * 8), ov);
    }
}

extern "C" void kernel_launch(void* const* d_in, const int* in_sizes, int n_in,
                              void* d_out, int out_size)
{
    const float* x = (const float*)d_in[0];
    const float* w = (const float*)d_in[1];
    float* out = (float*)d_out;

    long long n = (long long)out_size;               // 4*4096*4096 = 67108864
    unsigned blocks = (unsigned)(n / (THREADS * UNROLL * 8));  // 8192, exact cover

    scale_lastdim_v8_kernel<<<blocks, THREADS>>>(x, w, out);
}